// round 16
// baseline (speedup 1.0000x reference)
#include <cuda_runtime.h>

// ProbsNet fused single-kernel — plateau config (ncu ~31.1-31.6us, DRAM
// ~73%, 5.8 TB/s) with grid split by pair: blocks [0,HALF) stream ST0/W0,
// blocks [HALF,GRID) stream ST1/W1 concurrently -> 4 simultaneous DRAM
// sweep windows instead of 2 (last untested chip-level variable).
//   out = sum_i c0[i]*tmp0[i] + c1[i]*tmp1[i]
//   tmpX[i] = sum_d sigmoid(pB*(pBEV*BEV + STX[i,d])) * WX[i,d]
// sigmoid(x) = 0.5*tanh(0.5x)+0.5 (MUFU.TANH). 176 MB fp32 read-once.
// Structure: 3-stage register pipeline (prefetch distance 2), TILE=512
// float4, 3 blocks/SM single wave, deterministic two-level reduction.

#define D        131072
#define NROWS    84
#define VPR      (D / 4)              // 32768 float4 per row
#define NVEC     (NROWS * VPR)        // 2752512 float4 per (ST,W) pair
#define BLOCK    256
#define UNROLL   2
#define TILE     (BLOCK * UNROLL)     // 512 float4 per tile
#define TILES1   (NVEC / TILE)        // 5376 tiles per pair (exact, 64/row)
#define GRID     444                  // 148 SMs * 3 blocks
#define HALF     (GRID / 2)           // 222 blocks per pair

__device__ float        g_part[GRID];
__device__ unsigned int g_sem = 0;    // self-resetting (graph-replay safe)

// Entry e (0..83) of calc_probs(logits), flattened (4,21) layout.
__device__ __forceinline__ float probs_entry(const float* __restrict__ logits, int e) {
    float e0 = __expf(logits[0]);
    float e1 = __expf(logits[1]);
    float e2 = __expf(logits[2]);
    float e3 = __expf(logits[3]);
    float inv = __fdividef(1.0f, e0 + e1 + e2 + e3);
    float p[4] = {e0 * inv, e1 * inv, e2 * inv, e3 * inv};
    int i = e / 21;
    int r = e - i * 21;
    float v = p[i];
    if (r > 0) {
        int q  = r - 1;
        int j  = q / 5;
        int rr = q - j * 5;
        v *= p[j];
        if (rr > 0) v *= p[rr - 1];
    }
    return v;
}

__device__ __forceinline__ float tanh_fast(float x) {
    float y;
    asm("tanh.approx.f32 %0, %1;" : "=f"(y) : "f"(x));
    return y;
}

// sigmoid(pB*(bev+s)) = 0.5*tanh(a*s+b)+0.5,  a = 0.5*pB, b = a*bev
__device__ __forceinline__ float sig_dot4(float4 s4, float4 w4, float a, float b) {
    float t;
    t  = w4.x * fmaf(0.5f, tanh_fast(fmaf(a, s4.x, b)), 0.5f);
    t = fmaf(w4.y, fmaf(0.5f, tanh_fast(fmaf(a, s4.y, b)), 0.5f), t);
    t = fmaf(w4.z, fmaf(0.5f, tanh_fast(fmaf(a, s4.z, b)), 0.5f), t);
    t = fmaf(w4.w, fmaf(0.5f, tanh_fast(fmaf(a, s4.w, b)), 0.5f), t);
    return t;
}

struct TileRegs {
    float4 s0, s1, w0, w1;
    float  c;
};

// Lean single-pair load: pointers fixed for the whole block.
__device__ __forceinline__ void load_tile(
        TileRegs& r, int ti, int tid,
        const float4* __restrict__ st, const float4* __restrict__ w,
        const float* __restrict__ sp) {
    const int v0 = ti * TILE;
    r.c  = sp[ti >> 6];                 // 64 tiles per row
    r.s0 = st[v0 + tid];
    r.s1 = st[v0 + BLOCK + tid];
    r.w0 = w[v0 + tid];
    r.w1 = w[v0 + BLOCK + tid];
}

__device__ __forceinline__ float compute_tile(const TileRegs& r, float a, float b) {
    return r.c * (sig_dot4(r.s0, r.w0, a, b) + sig_dot4(r.s1, r.w1, a, b));
}

__global__ void __launch_bounds__(BLOCK, 3)
fused_kernel(const float* __restrict__ BEV,
             const float* __restrict__ ST0, const float* __restrict__ W0,
             const float* __restrict__ ST1, const float* __restrict__ W1,
             const float* __restrict__ probs0, const float* __restrict__ probs1,
             const float* __restrict__ probs2, const float* __restrict__ probs3,
             const float* __restrict__ probs4,
             const float* __restrict__ pBEV, const float* __restrict__ pB,
             float* __restrict__ out) {
    __shared__ float sc[2 * NROWS];
    const int tid = threadIdx.x;

    if (tid < NROWS) {
        sc[tid] = 0.2f * probs_entry(probs0, tid);
        float c1 = probs_entry(probs1, tid) + probs_entry(probs2, tid)
                 + probs_entry(probs3, tid) + probs_entry(probs4, tid);
        sc[NROWS + tid] = 0.2f * c1;
    }
    __syncthreads();

    const float a = 0.5f * pB[0];                 // tanh-form scale
    const float b = a * (pBEV[0] * BEV[0]);

    // Grid split by pair: 4 concurrent DRAM sweep windows chip-wide.
    const bool second = (blockIdx.x >= HALF);
    const int  g      = second ? (blockIdx.x - HALF) : blockIdx.x;  // 0..HALF-1
    const float4* __restrict__ st = (const float4*)(second ? ST1 : ST0);
    const float4* __restrict__ w  = (const float4*)(second ? W1  : W0);
    const float*  __restrict__ sp = sc + (second ? NROWS : 0);

    float acc = 0.0f;

    // --- 3-stage software pipeline, prefetch distance 2, stride HALF ---
    TileRegs b0, b1, b2;
    int ti = g;                                   // HALF << TILES1
    load_tile(b0, ti, tid, st, w, sp);
    bool v1 = (ti + HALF < TILES1);
    if (v1) load_tile(b1, ti + HALF, tid, st, w, sp);

    while (true) {
        bool v2 = (ti + 2 * HALF < TILES1);
        if (v2) load_tile(b2, ti + 2 * HALF, tid, st, w, sp);
        acc += compute_tile(b0, a, b);
        if (!v1) break;

        bool v3 = (ti + 3 * HALF < TILES1);
        if (v3) load_tile(b0, ti + 3 * HALF, tid, st, w, sp);
        acc += compute_tile(b1, a, b);
        if (!v2) break;

        bool v4 = (ti + 4 * HALF < TILES1);
        if (v4) load_tile(b1, ti + 4 * HALF, tid, st, w, sp);
        acc += compute_tile(b2, a, b);
        if (!v3) break;

        ti += 3 * HALF;
        v1 = v4;
    }

    // --- block reduce (fixed tree, deterministic) ---
    for (int off = 16; off > 0; off >>= 1)
        acc += __shfl_down_sync(0xFFFFFFFFu, acc, off);

    __shared__ float sm[BLOCK / 32];
    int lane = tid & 31;
    int wid  = tid >> 5;
    if (lane == 0) sm[wid] = acc;
    __syncthreads();
    if (wid == 0) {
        float bsum = (lane < BLOCK / 32) ? sm[lane] : 0.0f;
        for (int off = 4; off > 0; off >>= 1)
            bsum += __shfl_down_sync(0xFFFFFFFFu, bsum, off);
        if (lane == 0) g_part[blockIdx.x] = bsum;
    }

    // --- last block folds partials (deterministic fixed-order) ---
    __shared__ bool is_last;
    __threadfence();
    if (tid == 0)
        is_last = (atomicAdd(&g_sem, 1u) == GRID - 1);
    __syncthreads();

    if (is_last) {
        __threadfence();
        float a2 = 0.0f;
        for (int i = tid; i < GRID; i += BLOCK)
            a2 += g_part[i];
        for (int off = 16; off > 0; off >>= 1)
            a2 += __shfl_down_sync(0xFFFFFFFFu, a2, off);
        if (lane == 0) sm[wid] = a2;
        __syncthreads();
        if (tid == 0) {
            float s = 0.0f;
            #pragma unroll
            for (int i = 0; i < BLOCK / 32; i++) s += sm[i];
            out[0] = s;
            g_sem  = 0;
        }
    }
}

// Input order: BEV, ST0, Weight0, ST1, Weight1, Problem, probs0..4, pBEV, pB
extern "C" void kernel_launch(void* const* d_in, const int* in_sizes, int n_in,
                              void* d_out, int out_size) {
    const float* BEV    = (const float*)d_in[0];
    const float* ST0    = (const float*)d_in[1];
    const float* W0     = (const float*)d_in[2];
    const float* ST1    = (const float*)d_in[3];
    const float* W1     = (const float*)d_in[4];
    const float* probs0 = (const float*)d_in[6];
    const float* probs1 = (const float*)d_in[7];
    const float* probs2 = (const float*)d_in[8];
    const float* probs3 = (const float*)d_in[9];
    const float* probs4 = (const float*)d_in[10];
    const float* pBEV   = (const float*)d_in[11];
    const float* pB     = (const float*)d_in[12];

    fused_kernel<<<GRID, BLOCK>>>(BEV, ST0, W0, ST1, W1,
                                  probs0, probs1, probs2, probs3, probs4,
                                  pBEV, pB, (float*)d_out);
}

// round 17
// speedup vs baseline: 1.0471x; 1.0471x over previous
#include <cuda_runtime.h>

// ProbsNet fused single-kernel — FINAL (best-measured config, R9/R14:
// ncu 31.1us, DRAM 73.5%, 5.82 TB/s = empirical ceiling for this pattern).
//   out = sum_i c0[i]*tmp0[i] + c1[i]*tmp1[i]
//   tmpX[i] = sum_d sigmoid(pB*(pBEV*BEV + STX[i,d])) * WX[i,d]
// sigmoid(x) = 0.5*tanh(0.5x)+0.5 (MUFU.TANH).
// 176 MB fp32 read-once streaming. Exhaustive sweep (occupancy 35-80%,
// prefetch depth 1-3, tile 256-1024, LDG/cp.async paths, exp2/tanh,
// __ldcs, grid-split) confirms this is the peak operating point.
// Structure: 3-stage register pipeline (prefetch distance 2), TILE=512
// float4, 3 blocks/SM single wave, deterministic two-level reduction
// with self-resetting semaphore (graph-replay safe).

#define D        131072
#define NROWS    84
#define VPR      (D / 4)              // 32768 float4 per row
#define NVEC     (NROWS * VPR)        // 2752512 float4 per (ST,W) pair
#define BLOCK    256
#define UNROLL   2
#define TILE     (BLOCK * UNROLL)     // 512 float4 per tile
#define TILES1   (NVEC / TILE)        // 5376 tiles per pair (exact, 64/row)
#define TILES    (2 * TILES1)         // 10752
#define GRID     444                  // 148 SMs * 3 blocks

__device__ float        g_part[GRID];
__device__ unsigned int g_sem = 0;    // self-resetting (graph-replay safe)

// Entry e (0..83) of calc_probs(logits), flattened (4,21) layout.
__device__ __forceinline__ float probs_entry(const float* __restrict__ logits, int e) {
    float e0 = __expf(logits[0]);
    float e1 = __expf(logits[1]);
    float e2 = __expf(logits[2]);
    float e3 = __expf(logits[3]);
    float inv = __fdividef(1.0f, e0 + e1 + e2 + e3);
    float p[4] = {e0 * inv, e1 * inv, e2 * inv, e3 * inv};
    int i = e / 21;
    int r = e - i * 21;
    float v = p[i];
    if (r > 0) {
        int q  = r - 1;
        int j  = q / 5;
        int rr = q - j * 5;
        v *= p[j];
        if (rr > 0) v *= p[rr - 1];
    }
    return v;
}

__device__ __forceinline__ float tanh_fast(float x) {
    float y;
    asm("tanh.approx.f32 %0, %1;" : "=f"(y) : "f"(x));
    return y;
}

// sigmoid(pB*(bev+s)) = 0.5*tanh(a*s+b)+0.5,  a = 0.5*pB, b = a*bev
__device__ __forceinline__ float sig_dot4(float4 s4, float4 w4, float a, float b) {
    float t;
    t  = w4.x * fmaf(0.5f, tanh_fast(fmaf(a, s4.x, b)), 0.5f);
    t = fmaf(w4.y, fmaf(0.5f, tanh_fast(fmaf(a, s4.y, b)), 0.5f), t);
    t = fmaf(w4.z, fmaf(0.5f, tanh_fast(fmaf(a, s4.z, b)), 0.5f), t);
    t = fmaf(w4.w, fmaf(0.5f, tanh_fast(fmaf(a, s4.w, b)), 0.5f), t);
    return t;
}

struct TileRegs {
    float4 s0, s1, w0, w1;
    float  c;
};

__device__ __forceinline__ void load_tile(
        TileRegs& r, int t, int tid,
        const float4* __restrict__ st0, const float4* __restrict__ w0,
        const float4* __restrict__ st1, const float4* __restrict__ w1,
        const float* __restrict__ sc) {
    const bool second = (t >= TILES1);
    const int  ti     = second ? (t - TILES1) : t;
    const int  v0     = ti * TILE;
    const float4* __restrict__ st = second ? st1 : st0;
    const float4* __restrict__ w  = second ? w1  : w0;
    r.c  = sc[(second ? NROWS : 0) + (v0 >> 15)];
    r.s0 = st[v0 + tid];
    r.s1 = st[v0 + BLOCK + tid];
    r.w0 = w[v0 + tid];
    r.w1 = w[v0 + BLOCK + tid];
}

__device__ __forceinline__ float compute_tile(const TileRegs& r, float a, float b) {
    return r.c * (sig_dot4(r.s0, r.w0, a, b) + sig_dot4(r.s1, r.w1, a, b));
}

__global__ void __launch_bounds__(BLOCK, 3)
fused_kernel(const float* __restrict__ BEV,
             const float* __restrict__ ST0, const float* __restrict__ W0,
             const float* __restrict__ ST1, const float* __restrict__ W1,
             const float* __restrict__ probs0, const float* __restrict__ probs1,
             const float* __restrict__ probs2, const float* __restrict__ probs3,
             const float* __restrict__ probs4,
             const float* __restrict__ pBEV, const float* __restrict__ pB,
             float* __restrict__ out) {
    __shared__ float sc[2 * NROWS];
    const int tid = threadIdx.x;

    if (tid < NROWS) {
        sc[tid] = 0.2f * probs_entry(probs0, tid);
        float c1 = probs_entry(probs1, tid) + probs_entry(probs2, tid)
                 + probs_entry(probs3, tid) + probs_entry(probs4, tid);
        sc[NROWS + tid] = 0.2f * c1;
    }
    __syncthreads();

    const float a = 0.5f * pB[0];                 // tanh-form scale
    const float b = a * (pBEV[0] * BEV[0]);

    const float4* __restrict__ st0 = (const float4*)ST0;
    const float4* __restrict__ w0  = (const float4*)W0;
    const float4* __restrict__ st1 = (const float4*)ST1;
    const float4* __restrict__ w1  = (const float4*)W1;

    float acc = 0.0f;

    // --- 3-stage software pipeline, prefetch distance 2 ---
    TileRegs b0, b1, b2;
    int t = blockIdx.x;                           // GRID << TILES
    load_tile(b0, t, tid, st0, w0, st1, w1, sc);
    bool v1 = (t + GRID < TILES);
    if (v1) load_tile(b1, t + GRID, tid, st0, w0, st1, w1, sc);

    while (true) {
        // phase 0: prefetch t+2G, compute b0 (tile t)
        bool v2 = (t + 2 * GRID < TILES);
        if (v2) load_tile(b2, t + 2 * GRID, tid, st0, w0, st1, w1, sc);
        acc += compute_tile(b0, a, b);
        if (!v1) break;

        // phase 1: prefetch t+3G into b0, compute b1 (tile t+G)
        bool v3 = (t + 3 * GRID < TILES);
        if (v3) load_tile(b0, t + 3 * GRID, tid, st0, w0, st1, w1, sc);
        acc += compute_tile(b1, a, b);
        if (!v2) break;

        // phase 2: prefetch t+4G into b1, compute b2 (tile t+2G)
        bool v4 = (t + 4 * GRID < TILES);
        if (v4) load_tile(b1, t + 4 * GRID, tid, st0, w0, st1, w1, sc);
        acc += compute_tile(b2, a, b);
        if (!v3) break;

        t += 3 * GRID;
        v1 = v4;
    }

    // --- block reduce (fixed tree, deterministic) ---
    for (int off = 16; off > 0; off >>= 1)
        acc += __shfl_down_sync(0xFFFFFFFFu, acc, off);

    __shared__ float sm[BLOCK / 32];
    int lane = tid & 31;
    int wid  = tid >> 5;
    if (lane == 0) sm[wid] = acc;
    __syncthreads();
    if (wid == 0) {
        float bsum = (lane < BLOCK / 32) ? sm[lane] : 0.0f;
        for (int off = 4; off > 0; off >>= 1)
            bsum += __shfl_down_sync(0xFFFFFFFFu, bsum, off);
        if (lane == 0) g_part[blockIdx.x] = bsum;
    }

    // --- last block folds partials (deterministic fixed-order) ---
    __shared__ bool is_last;
    __threadfence();
    if (tid == 0)
        is_last = (atomicAdd(&g_sem, 1u) == GRID - 1);
    __syncthreads();

    if (is_last) {
        __threadfence();
        float a2 = 0.0f;
        for (int i = tid; i < GRID; i += BLOCK)
            a2 += g_part[i];
        for (int off = 16; off > 0; off >>= 1)
            a2 += __shfl_down_sync(0xFFFFFFFFu, a2, off);
        if (lane == 0) sm[wid] = a2;
        __syncthreads();
        if (tid == 0) {
            float s = 0.0f;
            #pragma unroll
            for (int i = 0; i < BLOCK / 32; i++) s += sm[i];
            out[0] = s;
            g_sem  = 0;
        }
    }
}

// Input order: BEV, ST0, Weight0, ST1, Weight1, Problem, probs0..4, pBEV, pB
extern "C" void kernel_launch(void* const* d_in, const int* in_sizes, int n_in,
                              void* d_out, int out_size) {
    const float* BEV    = (const float*)d_in[0];
    const float* ST0    = (const float*)d_in[1];
    const float* W0     = (const float*)d_in[2];
    const float* ST1    = (const float*)d_in[3];
    const float* W1     = (const float*)d_in[4];
    const float* probs0 = (const float*)d_in[6];
    const float* probs1 = (const float*)d_in[7];
    const float* probs2 = (const float*)d_in[8];
    const float* probs3 = (const float*)d_in[9];
    const float* probs4 = (const float*)d_in[10];
    const float* pBEV   = (const float*)d_in[11];
    const float* pB     = (const float*)d_in[12];

    fused_kernel<<<GRID, BLOCK>>>(BEV, ST0, W0, ST1, W1,
                                  probs0, probs1, probs2, probs3, probs4,
                                  pBEV, pB, (float*)d_out);
}